// round 1
// baseline (speedup 1.0000x reference)
#include <cuda_runtime.h>
#include <math.h>

#define BB 8
#define CH 64
#define HH 128
#define WW 128

// ---------------- scratch (device globals; no allocation allowed) ----------
__device__ float g_x_nhwc[BB*HH*WW*CH];   // x transposed to NHWC
__device__ float g_xh_nhwc[BB*HH*WW*CH];  // horizontal-pass output, NHWC
__device__ float g_omh[BB*HH*WW*12];      // per-pixel: dy0,dx0,dy1,dx1,dy2,dx2,m0,m1,m2,pad3
__device__ float g_omv[BB*HH*WW*12];

// ---------------- f32x2 packed helpers (Blackwell FFMA2) -------------------
static __device__ __forceinline__ unsigned long long pk2(float a, float b) {
    unsigned long long r;
    asm("mov.b64 %0, {%1,%2};" : "=l"(r) : "f"(a), "f"(b));
    return r;
}
static __device__ __forceinline__ void upk2(unsigned long long v, float &a, float &b) {
    asm("mov.b64 {%0,%1}, %2;" : "=f"(a), "=f"(b) : "l"(v));
}
static __device__ __forceinline__ unsigned long long ffma2(unsigned long long a,
                                                           unsigned long long b,
                                                           unsigned long long c) {
    unsigned long long d;
    asm("fma.rn.f32x2 %0, %1, %2, %3;" : "=l"(d) : "l"(a), "l"(b), "l"(c));
    return d;
}

static __device__ __forceinline__ float f4c(const float4 &v, int i) {
    return i == 0 ? v.x : (i == 1 ? v.y : (i == 2 ? v.z : v.w));
}

// ---------------- K0: NCHW -> NHWC transpose -------------------------------
__global__ __launch_bounds__(256) void transpose_kernel(const float* __restrict__ in) {
    __shared__ float tile[CH][33];
    int n = blockIdx.z, y = blockIdx.y, x0 = blockIdx.x * 32;
    int tx = threadIdx.x, ty = threadIdx.y;  // 32 x 8
    #pragma unroll
    for (int c = ty; c < CH; c += 8)
        tile[c][tx] = in[(((size_t)n*CH + c)*HH + y)*WW + x0 + tx];
    __syncthreads();
    int t = ty*32 + tx;
    #pragma unroll
    for (int i = 0; i < 8; i++) {
        int idx = t + i*256;
        int px = idx >> 6, c = idx & 63;
        g_x_nhwc[(((size_t)n*HH + y)*WW + x0 + px)*CH + c] = tile[c][px];
    }
}

// ---------------- K1: offsets + masks for both passes ----------------------
// 18 conv outputs per pixel: h: 6 off + 3 mask (1x3 window), v: same (3x1 window)
__global__ __launch_bounds__(256) void offmask_kernel(
    const float* __restrict__ woh, const float* __restrict__ boh,
    const float* __restrict__ wmh, const float* __restrict__ bmh,
    const float* __restrict__ wov, const float* __restrict__ bov,
    const float* __restrict__ wmv, const float* __restrict__ bmv)
{
    // ws[c][j(6: 0-2 horiz,3-5 vert)][o(12: 0-5 off,6-8 mask,9-11 zero pad)]
    __shared__ float ws[64*6*12];
    int tid = threadIdx.x;
    for (int i = tid; i < 64*6*12; i += 256) {
        int o = i % 12, j = (i/12) % 6, c = i/72;
        float v = 0.f;
        if (o < 6)      v = (j < 3) ? woh[o*192 + c*3 + j] : wov[o*192 + c*3 + (j-3)];
        else if (o < 9) v = (j < 3) ? wmh[(o-6)*192 + c*3 + j] : wmv[(o-6)*192 + c*3 + (j-3)];
        ws[i] = v;
    }
    __syncthreads();

    int row = blockIdx.x*2 + (tid >> 7);       // 0..1023
    int x   = tid & 127;
    int n = row >> 7, y = row & 127;
    size_t p = (size_t)row*WW + x;

    float accH[12], accV[12];
    #pragma unroll
    for (int i = 0; i < 12; i++) { accH[i] = 0.f; accV[i] = 0.f; }

    const float* pc = g_x_nhwc + p*CH;
    bool hl = x > 0, hr = x < WW-1, vu = y > 0, vd = y < HH-1;
    const float* pl = pc - CH;
    const float* pr = pc + CH;
    const float* pu = pc - (size_t)WW*CH;
    const float* pd = pc + (size_t)WW*CH;
    const float4 Z = make_float4(0.f,0.f,0.f,0.f);

    for (int c4 = 0; c4 < 16; c4++) {
        float4 fc = *(const float4*)(pc + c4*4);
        float4 fl = hl ? *(const float4*)(pl + c4*4) : Z;
        float4 fr = hr ? *(const float4*)(pr + c4*4) : Z;
        float4 fu = vu ? *(const float4*)(pu + c4*4) : Z;
        float4 fd = vd ? *(const float4*)(pd + c4*4) : Z;
        #pragma unroll
        for (int cc = 0; cc < 4; cc++) {
            int c = c4*4 + cc;
            float vh[3] = { f4c(fl,cc), f4c(fc,cc), f4c(fr,cc) };
            float vv[3] = { f4c(fu,cc), f4c(fc,cc), f4c(fd,cc) };
            #pragma unroll
            for (int j = 0; j < 3; j++) {
                const float4* wp = (const float4*)&ws[(c*6 + j)*12];
                float4 w0 = wp[0], w1 = wp[1], w2 = wp[2];
                float v = vh[j];
                accH[0] = fmaf(w0.x,v,accH[0]); accH[1] = fmaf(w0.y,v,accH[1]);
                accH[2] = fmaf(w0.z,v,accH[2]); accH[3] = fmaf(w0.w,v,accH[3]);
                accH[4] = fmaf(w1.x,v,accH[4]); accH[5] = fmaf(w1.y,v,accH[5]);
                accH[6] = fmaf(w1.z,v,accH[6]); accH[7] = fmaf(w1.w,v,accH[7]);
                accH[8] = fmaf(w2.x,v,accH[8]);
                const float4* wq = (const float4*)&ws[(c*6 + j + 3)*12];
                float4 u0 = wq[0], u1 = wq[1], u2 = wq[2];
                float u = vv[j];
                accV[0] = fmaf(u0.x,u,accV[0]); accV[1] = fmaf(u0.y,u,accV[1]);
                accV[2] = fmaf(u0.z,u,accV[2]); accV[3] = fmaf(u0.w,u,accV[3]);
                accV[4] = fmaf(u1.x,u,accV[4]); accV[5] = fmaf(u1.y,u,accV[5]);
                accV[6] = fmaf(u1.z,u,accV[6]); accV[7] = fmaf(u1.w,u,accV[7]);
                accV[8] = fmaf(u2.x,u,accV[8]);
            }
        }
    }

    // biases + sigmoid on masks; store stride-12 records
    float mh0 = 1.f/(1.f + expf(-(accH[6] + __ldg(bmh+0))));
    float mh1 = 1.f/(1.f + expf(-(accH[7] + __ldg(bmh+1))));
    float mh2 = 1.f/(1.f + expf(-(accH[8] + __ldg(bmh+2))));
    float mv0 = 1.f/(1.f + expf(-(accV[6] + __ldg(bmv+0))));
    float mv1 = 1.f/(1.f + expf(-(accV[7] + __ldg(bmv+1))));
    float mv2 = 1.f/(1.f + expf(-(accV[8] + __ldg(bmv+2))));

    float* oh = g_omh + p*12;
    *(float4*)(oh + 0) = make_float4(accH[0]+__ldg(boh+0), accH[1]+__ldg(boh+1),
                                     accH[2]+__ldg(boh+2), accH[3]+__ldg(boh+3));
    *(float4*)(oh + 4) = make_float4(accH[4]+__ldg(boh+4), accH[5]+__ldg(boh+5), mh0, mh1);
    oh[8] = mh2;
    float* ov = g_omv + p*12;
    *(float4*)(ov + 0) = make_float4(accV[0]+__ldg(bov+0), accV[1]+__ldg(bov+1),
                                     accV[2]+__ldg(bov+2), accV[3]+__ldg(bov+3));
    *(float4*)(ov + 4) = make_float4(accV[4]+__ldg(bov+4), accV[5]+__ldg(bov+5), mv0, mv1);
    ov[8] = mv2;
}

// ---------------- K2/K3: deformable axial pass -----------------------------
// VERT=0: taps along x (kx_base=k-1), VERT=1: taps along y.
// OUT_NCHW=0: write NHWC (+bias), OUT_NCHW=1: write NCHW (+bias) to d_out.
template<int VERT, int OUT_NCHW>
__global__ __launch_bounds__(128) void pass_kernel(
    const float* __restrict__ src,   // NHWC input
    const float* __restrict__ om,    // stride-12 offset/mask records
    const float* __restrict__ wg,    // [64 o][64 c][3 k] fp32
    const float* __restrict__ bias,  // [64]
    float* __restrict__ dst)
{
    __shared__ float ws[3*64*64];    // [k][c][o], o contiguous (48 KB)
    int tid = threadIdx.x;
    for (int i = tid; i < 64*64*3; i += 128) {
        int k = i % 3, c = (i/3) % 64, o = i/192;
        ws[(k*64 + c)*64 + o] = wg[i];
    }
    __syncthreads();

    int row = blockIdx.x;            // n*H + y
    int n = row >> 7, y = row & 127;
    int x = tid;
    size_t p = (size_t)row*WW + x;

    const float* omb = om + p*12;
    float4 A  = *(const float4*)omb;
    float4 Bq = *(const float4*)(omb + 4);
    float dy[3] = { A.x, A.z, Bq.x };
    float dx[3] = { A.y, A.w, Bq.y };
    float mk[3] = { Bq.z, Bq.w, omb[8] };

    unsigned long long acc[32];
    #pragma unroll
    for (int i = 0; i < 32; i++) acc[i] = 0ull;

    #pragma unroll
    for (int k = 0; k < 3; k++) {
        float py = (float)y + dy[k] + (VERT ? (float)(k-1) : 0.f);
        float px = (float)x + dx[k] + (VERT ? 0.f : (float)(k-1));
        float y0f = floorf(py), x0f = floorf(px);
        float wy = py - y0f, wx = px - x0f;
        int iy0 = (int)y0f, ix0 = (int)x0f;
        int iy1 = iy0 + 1,  ix1 = ix0 + 1;
        float vy0 = (iy0 >= 0 && iy0 < HH) ? 1.f : 0.f;
        float vy1 = (iy1 >= 0 && iy1 < HH) ? 1.f : 0.f;
        float vx0 = (ix0 >= 0 && ix0 < WW) ? 1.f : 0.f;
        float vx1 = (ix1 >= 0 && ix1 < WW) ? 1.f : 0.f;
        float mm = mk[k];
        float w00 = (1.f-wy)*(1.f-wx)*vy0*vx0*mm;
        float w01 = (1.f-wy)*wx      *vy0*vx1*mm;
        float w10 = wy*(1.f-wx)      *vy1*vx0*mm;
        float w11 = wy*wx            *vy1*vx1*mm;
        int cy0 = min(max(iy0,0),HH-1), cy1 = min(max(iy1,0),HH-1);
        int cx0 = min(max(ix0,0),WW-1), cx1 = min(max(ix1,0),WW-1);
        const float* p00 = src + ((size_t)(n*HH+cy0)*WW + cx0)*CH;
        const float* p01 = src + ((size_t)(n*HH+cy0)*WW + cx1)*CH;
        const float* p10 = src + ((size_t)(n*HH+cy1)*WW + cx0)*CH;
        const float* p11 = src + ((size_t)(n*HH+cy1)*WW + cx1)*CH;
        const float* wk = &ws[k*64*64];

        for (int c4 = 0; c4 < 16; c4++) {
            float4 a = *(const float4*)(p00 + c4*4);
            float4 b = *(const float4*)(p01 + c4*4);
            float4 c = *(const float4*)(p10 + c4*4);
            float4 d = *(const float4*)(p11 + c4*4);
            #pragma unroll
            for (int cc = 0; cc < 4; cc++) {
                float val = fmaf(w00, f4c(a,cc),
                            fmaf(w01, f4c(b,cc),
                            fmaf(w10, f4c(c,cc), w11 * f4c(d,cc))));
                unsigned long long V = pk2(val, val);
                const float4* wp = (const float4*)(wk + (c4*4 + cc)*64);
                #pragma unroll
                for (int i = 0; i < 16; i++) {
                    float4 wq = wp[i];
                    acc[2*i]   = ffma2(V, pk2(wq.x, wq.y), acc[2*i]);
                    acc[2*i+1] = ffma2(V, pk2(wq.z, wq.w), acc[2*i+1]);
                }
            }
        }
    }

    if (OUT_NCHW) {
        #pragma unroll
        for (int i = 0; i < 32; i++) {
            float v0, v1; upk2(acc[i], v0, v1);
            dst[(((size_t)n*CH + 2*i  )*HH + y)*WW + x] = v0 + __ldg(bias + 2*i);
            dst[(((size_t)n*CH + 2*i+1)*HH + y)*WW + x] = v1 + __ldg(bias + 2*i+1);
        }
    } else {
        float* db = dst + p*CH;
        #pragma unroll
        for (int i = 0; i < 16; i++) {
            float v0,v1,v2,v3;
            upk2(acc[2*i],   v0, v1);
            upk2(acc[2*i+1], v2, v3);
            *(float4*)(db + 4*i) = make_float4(v0 + __ldg(bias+4*i),
                                               v1 + __ldg(bias+4*i+1),
                                               v2 + __ldg(bias+4*i+2),
                                               v3 + __ldg(bias+4*i+3));
        }
    }
}

// ---------------- launch ---------------------------------------------------
extern "C" void kernel_launch(void* const* d_in, const int* in_sizes, int n_in,
                              void* d_out, int out_size) {
    const float* x        = (const float*)d_in[0];
    const float* w_off_h  = (const float*)d_in[1];
    const float* b_off_h  = (const float*)d_in[2];
    const float* w_mask_h = (const float*)d_in[3];
    const float* b_mask_h = (const float*)d_in[4];
    const float* w_off_v  = (const float*)d_in[5];
    const float* b_off_v  = (const float*)d_in[6];
    const float* w_mask_v = (const float*)d_in[7];
    const float* b_mask_v = (const float*)d_in[8];
    const float* w_h      = (const float*)d_in[9];
    const float* b_h      = (const float*)d_in[10];
    const float* w_v      = (const float*)d_in[11];
    const float* b_v      = (const float*)d_in[12];
    float* out = (float*)d_out;

    void *xn_p, *xh_p, *omh_p, *omv_p;
    cudaGetSymbolAddress(&xn_p,  g_x_nhwc);
    cudaGetSymbolAddress(&xh_p,  g_xh_nhwc);
    cudaGetSymbolAddress(&omh_p, g_omh);
    cudaGetSymbolAddress(&omv_p, g_omv);
    const float* xn  = (const float*)xn_p;
    float*       xh  = (float*)xh_p;
    const float* omh = (const float*)omh_p;
    const float* omv = (const float*)omv_p;

    transpose_kernel<<<dim3(WW/32, HH, BB), dim3(32, 8)>>>(x);

    offmask_kernel<<<BB*HH/2, 256>>>(w_off_h, b_off_h, w_mask_h, b_mask_h,
                                     w_off_v, b_off_v, w_mask_v, b_mask_v);

    pass_kernel<0, 0><<<BB*HH, 128>>>(xn, omh, w_h, b_h, xh);
    pass_kernel<1, 1><<<BB*HH, 128>>>((const float*)xh, omv, w_v, b_v, out);
}

// round 2
// speedup vs baseline: 1.6924x; 1.6924x over previous
#include <cuda_runtime.h>
#include <math.h>

#define BB 8
#define CH 64
#define HH 128
#define WW 128

typedef unsigned long long u64;

// ---------------- scratch (device globals; no allocation allowed) ----------
__device__ float g_x_nhwc[BB*HH*WW*CH];   // x transposed to NHWC
__device__ float g_xh_nhwc[BB*HH*WW*CH];  // horizontal-pass output, NHWC
__device__ float g_omh[BB*HH*WW*12];      // dy0,dx0,dy1,dx1,dy2,dx2,m0,m1,m2,pad
__device__ float g_omv[BB*HH*WW*12];

// ---------------- f32x2 packed helpers (Blackwell FFMA2) -------------------
static __device__ __forceinline__ void upk2(u64 v, float &a, float &b) {
    asm("mov.b64 {%0,%1}, %2;" : "=f"(a), "=f"(b) : "l"(v));
}
static __device__ __forceinline__ u64 ffma2(u64 a, u64 b, u64 c) {
    u64 d;
    asm("fma.rn.f32x2 %0, %1, %2, %3;" : "=l"(d) : "l"(a), "l"(b), "l"(c));
    return d;
}
static __device__ __forceinline__ float f4c(const float4 &v, int i) {
    return i == 0 ? v.x : (i == 1 ? v.y : (i == 2 ? v.z : v.w));
}

// ---------------- K0: NCHW -> NHWC transpose -------------------------------
__global__ __launch_bounds__(256) void transpose_kernel(const float* __restrict__ in) {
    __shared__ float tile[CH][33];
    int n = blockIdx.z, y = blockIdx.y, x0 = blockIdx.x * 32;
    int tx = threadIdx.x, ty = threadIdx.y;  // 32 x 8
    #pragma unroll
    for (int c = ty; c < CH; c += 8)
        tile[c][tx] = in[(((size_t)n*CH + c)*HH + y)*WW + x0 + tx];
    __syncthreads();
    int t = ty*32 + tx;
    #pragma unroll
    for (int i = 0; i < 8; i++) {
        int idx = t + i*256;
        int px = idx >> 6, c = idx & 63;
        g_x_nhwc[(((size_t)n*HH + y)*WW + x0 + px)*CH + c] = tile[c][px];
    }
}

// ---------------- K1: offsets + masks for both passes ----------------------
__global__ __launch_bounds__(256) void offmask_kernel(
    const float* __restrict__ woh, const float* __restrict__ boh,
    const float* __restrict__ wmh, const float* __restrict__ bmh,
    const float* __restrict__ wov, const float* __restrict__ bov,
    const float* __restrict__ wmv, const float* __restrict__ bmv)
{
    __shared__ float ws[64*6*12];
    int tid = threadIdx.x;
    for (int i = tid; i < 64*6*12; i += 256) {
        int o = i % 12, j = (i/12) % 6, c = i/72;
        float v = 0.f;
        if (o < 6)      v = (j < 3) ? woh[o*192 + c*3 + j] : wov[o*192 + c*3 + (j-3)];
        else if (o < 9) v = (j < 3) ? wmh[(o-6)*192 + c*3 + j] : wmv[(o-6)*192 + c*3 + (j-3)];
        ws[i] = v;
    }
    __syncthreads();

    int row = blockIdx.x*2 + (tid >> 7);
    int x   = tid & 127;
    size_t p = (size_t)row*WW + x;
    int y = row & 127;

    float accH[9], accV[9];
    #pragma unroll
    for (int i = 0; i < 9; i++) { accH[i] = 0.f; accV[i] = 0.f; }

    const float* pc = g_x_nhwc + p*CH;
    bool hl = x > 0, hr = x < WW-1, vu = y > 0, vd = y < HH-1;
    const float* pl = pc - CH;
    const float* pr = pc + CH;
    const float* pu = pc - (size_t)WW*CH;
    const float* pd = pc + (size_t)WW*CH;
    const float4 Z = make_float4(0.f,0.f,0.f,0.f);

    for (int c4 = 0; c4 < 16; c4++) {
        float4 fc = *(const float4*)(pc + c4*4);
        float4 fl = hl ? *(const float4*)(pl + c4*4) : Z;
        float4 fr = hr ? *(const float4*)(pr + c4*4) : Z;
        float4 fu = vu ? *(const float4*)(pu + c4*4) : Z;
        float4 fd = vd ? *(const float4*)(pd + c4*4) : Z;
        #pragma unroll
        for (int cc = 0; cc < 4; cc++) {
            int c = c4*4 + cc;
            float vh[3] = { f4c(fl,cc), f4c(fc,cc), f4c(fr,cc) };
            float vv[3] = { f4c(fu,cc), f4c(fc,cc), f4c(fd,cc) };
            #pragma unroll
            for (int j = 0; j < 3; j++) {
                const float4* wp = (const float4*)&ws[(c*6 + j)*12];
                float4 w0 = wp[0], w1 = wp[1], w2 = wp[2];
                float v = vh[j];
                accH[0] = fmaf(w0.x,v,accH[0]); accH[1] = fmaf(w0.y,v,accH[1]);
                accH[2] = fmaf(w0.z,v,accH[2]); accH[3] = fmaf(w0.w,v,accH[3]);
                accH[4] = fmaf(w1.x,v,accH[4]); accH[5] = fmaf(w1.y,v,accH[5]);
                accH[6] = fmaf(w1.z,v,accH[6]); accH[7] = fmaf(w1.w,v,accH[7]);
                accH[8] = fmaf(w2.x,v,accH[8]);
                const float4* wq = (const float4*)&ws[(c*6 + j + 3)*12];
                float4 u0 = wq[0], u1 = wq[1], u2 = wq[2];
                float u = vv[j];
                accV[0] = fmaf(u0.x,u,accV[0]); accV[1] = fmaf(u0.y,u,accV[1]);
                accV[2] = fmaf(u0.z,u,accV[2]); accV[3] = fmaf(u0.w,u,accV[3]);
                accV[4] = fmaf(u1.x,u,accV[4]); accV[5] = fmaf(u1.y,u,accV[5]);
                accV[6] = fmaf(u1.z,u,accV[6]); accV[7] = fmaf(u1.w,u,accV[7]);
                accV[8] = fmaf(u2.x,u,accV[8]);
            }
        }
    }

    float mh0 = 1.f/(1.f + expf(-(accH[6] + __ldg(bmh+0))));
    float mh1 = 1.f/(1.f + expf(-(accH[7] + __ldg(bmh+1))));
    float mh2 = 1.f/(1.f + expf(-(accH[8] + __ldg(bmh+2))));
    float mv0 = 1.f/(1.f + expf(-(accV[6] + __ldg(bmv+0))));
    float mv1 = 1.f/(1.f + expf(-(accV[7] + __ldg(bmv+1))));
    float mv2 = 1.f/(1.f + expf(-(accV[8] + __ldg(bmv+2))));

    float* oh = g_omh + p*12;
    *(float4*)(oh + 0) = make_float4(accH[0]+__ldg(boh+0), accH[1]+__ldg(boh+1),
                                     accH[2]+__ldg(boh+2), accH[3]+__ldg(boh+3));
    *(float4*)(oh + 4) = make_float4(accH[4]+__ldg(boh+4), accH[5]+__ldg(boh+5), mh0, mh1);
    oh[8] = mh2;
    float* ov = g_omv + p*12;
    *(float4*)(ov + 0) = make_float4(accV[0]+__ldg(bov+0), accV[1]+__ldg(bov+1),
                                     accV[2]+__ldg(bov+2), accV[3]+__ldg(bov+3));
    *(float4*)(ov + 4) = make_float4(accV[4]+__ldg(bov+4), accV[5]+__ldg(bov+5), mv0, mv1);
    ov[8] = mv2;
}

// ---------------- K2/K3: deformable axial pass (GEMM-tiled) ----------------
// Block = 256 threads, tile = 128 pixels (one row) x 64 outputs.
// smem layout (dynamic):
//   ws2 [3][32][64][2]    : 12288 f  (channel-pair-interleaved weights)
//   valb[16][129][4]      : 8256 f   (staged bilinear samples, 1 tap)
//   cww [3][128][4]       : 1536 f   (per-pixel corner weights, premult mask)
//   cbase[3][128][4] ints : 1536 i
#define SM_WS2   0
#define SM_VALB  12288
#define SM_CWW   (12288 + 8256)
#define SM_CB    (SM_CWW + 1536)
#define SM_FLOATS (SM_CB + 1536)

template<int VERT, int OUT_NCHW>
__global__ __launch_bounds__(256, 2) void pass_kernel(
    const float* __restrict__ src,   // NHWC input
    const float* __restrict__ om,    // stride-12 offset/mask records
    const float* __restrict__ wg,    // [64 o][64 c][3 k]
    const float* __restrict__ bias,  // [64]
    float* __restrict__ dst)
{
    extern __shared__ float smem[];
    float* ws2  = smem + SM_WS2;
    float* valb = smem + SM_VALB;
    float* cww  = smem + SM_CWW;
    int*   cbase = (int*)(smem + SM_CB);

    int tid = threadIdx.x;
    int row = blockIdx.x;            // n*H + y
    int n = row >> 7, y = row & 127;

    // interleave weights: ws2[k][c2][o][e] = wg[o][2*c2+e][k]
    for (int i = tid; i < 12288; i += 256) {
        int e = i & 1, o = (i >> 1) & 63, c2 = (i >> 7) & 31, k = i >> 12;
        ws2[i] = wg[o*192 + (2*c2 + e)*3 + k];
    }

    // per-pixel, per-tap corner weights + clamped base offsets
    for (int t = tid; t < 384; t += 256) {
        int k = t >> 7, xp = t & 127;
        const float* omb = om + ((size_t)row*WW + xp)*12;
        float dyk = omb[2*k], dxk = omb[2*k + 1], mkk = omb[6 + k];
        float py = (float)y + dyk + (VERT ? (float)(k-1) : 0.f);
        float pxf = (float)xp + dxk + (VERT ? 0.f : (float)(k-1));
        float y0f = floorf(py), x0f = floorf(pxf);
        float wy = py - y0f, wx = pxf - x0f;
        int iy0 = (int)y0f, ix0 = (int)x0f;
        int iy1 = iy0 + 1,  ix1 = ix0 + 1;
        float vy0 = (iy0 >= 0 && iy0 < HH) ? 1.f : 0.f;
        float vy1 = (iy1 >= 0 && iy1 < HH) ? 1.f : 0.f;
        float vx0 = (ix0 >= 0 && ix0 < WW) ? 1.f : 0.f;
        float vx1 = (ix1 >= 0 && ix1 < WW) ? 1.f : 0.f;
        float* cw = &cww[(k*128 + xp)*4];
        cw[0] = (1.f-wy)*(1.f-wx)*vy0*vx0*mkk;
        cw[1] = (1.f-wy)*wx      *vy0*vx1*mkk;
        cw[2] = wy*(1.f-wx)      *vy1*vx0*mkk;
        cw[3] = wy*wx            *vy1*vx1*mkk;
        int cy0 = min(max(iy0,0),HH-1), cy1 = min(max(iy1,0),HH-1);
        int cx0 = min(max(ix0,0),WW-1), cx1 = min(max(ix1,0),WW-1);
        int* cb = &cbase[(k*128 + xp)*4];
        cb[0] = ((n*HH + cy0)*WW + cx0)*CH;
        cb[1] = ((n*HH + cy0)*WW + cx1)*CH;
        cb[2] = ((n*HH + cy1)*WW + cx0)*CH;
        cb[3] = ((n*HH + cy1)*WW + cx1)*CH;
    }
    __syncthreads();

    int lane = tid & 31, wid = tid >> 5;
    int p8 = lane >> 3, c8l = lane & 7;      // phase-A lane roles
    int pg = tid >> 4, og = tid & 15;        // phase-B tile: px=pg*8.., o=og*4..

    u64 acc[8][4];
    #pragma unroll
    for (int i = 0; i < 8; i++)
        #pragma unroll
        for (int j = 0; j < 4; j++) acc[i][j] = 0ull;

    for (int k = 0; k < 3; k++) {
        if (k) __syncthreads();   // valb reuse: previous GEMM done

        // -------- Phase A: stage bilinear samples for this tap --------
        #pragma unroll
        for (int i = 0; i < 4; i++) {
            int xp = wid*16 + i*4 + p8;
            const float* cw = &cww[(k*128 + xp)*4];
            const int*   cb = &cbase[(k*128 + xp)*4];
            float w00 = cw[0], w01 = cw[1], w10 = cw[2], w11 = cw[3];
            int b00 = cb[0], b01 = cb[1], b10 = cb[2], b11 = cb[3];
            #pragma unroll
            for (int h = 0; h < 2; h++) {
                int c8 = h*8 + c8l;
                int co = c8*4;
                float4 v00 = *(const float4*)(src + b00 + co);
                float4 v01 = *(const float4*)(src + b01 + co);
                float4 v10 = *(const float4*)(src + b10 + co);
                float4 v11 = *(const float4*)(src + b11 + co);
                float4 r;
                r.x = fmaf(w00,v00.x, fmaf(w01,v01.x, fmaf(w10,v10.x, w11*v11.x)));
                r.y = fmaf(w00,v00.y, fmaf(w01,v01.y, fmaf(w10,v10.y, w11*v11.y)));
                r.z = fmaf(w00,v00.z, fmaf(w01,v01.z, fmaf(w10,v10.z, w11*v11.z)));
                r.w = fmaf(w00,v00.w, fmaf(w01,v01.w, fmaf(w10,v10.w, w11*v11.w)));
                *(float4*)&valb[(c8*129 + xp)*4] = r;
            }
        }
        __syncthreads();

        // -------- Phase B: GEMM accumulate over this tap's 64 channels --------
        const float* wsk = ws2 + k*4096;   // [32][64][2]
        #pragma unroll 2
        for (int c2 = 0; c2 < 32; c2++) {
            int c8 = c2 >> 1, j2 = (c2 & 1)*2;
            const float* ab = &valb[(c8*129 + pg*8)*4 + j2];
            u64 Ap[8];
            #pragma unroll
            for (int i = 0; i < 8; i++)
                Ap[i] = *(const u64*)(ab + i*4);
            const float* bb = wsk + c2*128 + og*8;
            u64 Bp0 = *(const u64*)(bb);
            u64 Bp1 = *(const u64*)(bb + 2);
            u64 Bp2 = *(const u64*)(bb + 4);
            u64 Bp3 = *(const u64*)(bb + 6);
            #pragma unroll
            for (int i = 0; i < 8; i++) {
                acc[i][0] = ffma2(Ap[i], Bp0, acc[i][0]);
                acc[i][1] = ffma2(Ap[i], Bp1, acc[i][1]);
                acc[i][2] = ffma2(Ap[i], Bp2, acc[i][2]);
                acc[i][3] = ffma2(Ap[i], Bp3, acc[i][3]);
            }
        }
    }

    // -------- finalize: fold pairs, add bias, store --------
    float4 bv = *(const float4*)(bias + og*4);
    float s[8][4];
    #pragma unroll
    for (int i = 0; i < 8; i++) {
        #pragma unroll
        for (int j = 0; j < 4; j++) {
            float lo, hi; upk2(acc[i][j], lo, hi);
            s[i][j] = lo + hi + f4c(bv, j);
        }
    }

    if (OUT_NCHW) {
        #pragma unroll
        for (int j = 0; j < 4; j++) {
            float* db = dst + (((size_t)(n*CH + og*4 + j))*HH + y)*WW + pg*8;
            *(float4*)(db)     = make_float4(s[0][j], s[1][j], s[2][j], s[3][j]);
            *(float4*)(db + 4) = make_float4(s[4][j], s[5][j], s[6][j], s[7][j]);
        }
    } else {
        #pragma unroll
        for (int i = 0; i < 8; i++) {
            float* db = dst + ((size_t)row*WW + pg*8 + i)*CH + og*4;
            *(float4*)db = make_float4(s[i][0], s[i][1], s[i][2], s[i][3]);
        }
    }
}

// ---------------- launch ---------------------------------------------------
extern "C" void kernel_launch(void* const* d_in, const int* in_sizes, int n_in,
                              void* d_out, int out_size) {
    const float* x        = (const float*)d_in[0];
    const float* w_off_h  = (const float*)d_in[1];
    const float* b_off_h  = (const float*)d_in[2];
    const float* w_mask_h = (const float*)d_in[3];
    const float* b_mask_h = (const float*)d_in[4];
    const float* w_off_v  = (const float*)d_in[5];
    const float* b_off_v  = (const float*)d_in[6];
    const float* w_mask_v = (const float*)d_in[7];
    const float* b_mask_v = (const float*)d_in[8];
    const float* w_h      = (const float*)d_in[9];
    const float* b_h      = (const float*)d_in[10];
    const float* w_v      = (const float*)d_in[11];
    const float* b_v      = (const float*)d_in[12];
    float* out = (float*)d_out;

    void *xn_p, *xh_p, *omh_p, *omv_p;
    cudaGetSymbolAddress(&xn_p,  g_x_nhwc);
    cudaGetSymbolAddress(&xh_p,  g_xh_nhwc);
    cudaGetSymbolAddress(&omh_p, g_omh);
    cudaGetSymbolAddress(&omv_p, g_omv);
    const float* xn  = (const float*)xn_p;
    float*       xh  = (float*)xh_p;
    const float* omh = (const float*)omh_p;
    const float* omv = (const float*)omv_p;

    int smem_bytes = SM_FLOATS * 4;   // ~94.5 KB
    cudaFuncSetAttribute(pass_kernel<0,0>,
                         cudaFuncAttributeMaxDynamicSharedMemorySize, smem_bytes);
    cudaFuncSetAttribute(pass_kernel<1,1>,
                         cudaFuncAttributeMaxDynamicSharedMemorySize, smem_bytes);

    transpose_kernel<<<dim3(WW/32, HH, BB), dim3(32, 8)>>>(x);

    offmask_kernel<<<BB*HH/2, 256>>>(w_off_h, b_off_h, w_mask_h, b_mask_h,
                                     w_off_v, b_off_v, w_mask_v, b_mask_v);

    pass_kernel<0, 0><<<BB*HH, 256, smem_bytes>>>(xn, omh, w_h, b_h, xh);
    pass_kernel<1, 1><<<BB*HH, 256, smem_bytes>>>((const float*)xh, omv, w_v, b_v, out);
}

// round 3
// speedup vs baseline: 1.8315x; 1.0822x over previous
#include <cuda_runtime.h>
#include <math.h>

#define BB 8
#define CH 64
#define HH 128
#define WW 128

typedef unsigned long long u64;

// ---------------- scratch (device globals; no allocation allowed) ----------
__device__ float g_x_nhwc[BB*HH*WW*CH];   // x transposed to NHWC
__device__ float g_xh_nhwc[BB*HH*WW*CH];  // horizontal-pass output, NHWC
__device__ float g_omh[BB*HH*WW*12];      // dy0,dx0,dy1,dx1,dy2,dx2,m0,m1,m2,pad
__device__ float g_omv[BB*HH*WW*12];
__device__ float g_w2[2][12288];          // reformatted weights [pass][k][c2][o][e]

// ---------------- f32x2 packed helpers (Blackwell FFMA2) -------------------
static __device__ __forceinline__ u64 pk2(float a, float b) {
    u64 r;
    asm("mov.b64 %0, {%1,%2};" : "=l"(r) : "f"(a), "f"(b));
    return r;
}
static __device__ __forceinline__ void upk2(u64 v, float &a, float &b) {
    asm("mov.b64 {%0,%1}, %2;" : "=f"(a), "=f"(b) : "l"(v));
}
static __device__ __forceinline__ u64 ffma2(u64 a, u64 b, u64 c) {
    u64 d;
    asm("fma.rn.f32x2 %0, %1, %2, %3;" : "=l"(d) : "l"(a), "l"(b), "l"(c));
    return d;
}
static __device__ __forceinline__ float f4c(const float4 &v, int i) {
    return i == 0 ? v.x : (i == 1 ? v.y : (i == 2 ? v.z : v.w));
}

// ---------------- K-1: weight reformat (runs once, tiny) -------------------
// g_w2[p][((k*32 + c2)*64 + o)*2 + e] = w[o*192 + (2*c2+e)*3 + k]
__global__ __launch_bounds__(256) void prep_weights(
    const float* __restrict__ wh, const float* __restrict__ wv)
{
    int i = blockIdx.x*256 + threadIdx.x;
    if (i < 12288) {
        int e = i & 1, o = (i >> 1) & 63, c2 = (i >> 7) & 31, k = i >> 12;
        int s = o*192 + (2*c2 + e)*3 + k;
        g_w2[0][i] = wh[s];
        g_w2[1][i] = wv[s];
    }
}

// ---------------- K0: NCHW -> NHWC transpose -------------------------------
__global__ __launch_bounds__(256) void transpose_kernel(const float* __restrict__ in) {
    __shared__ float tile[CH][33];
    int n = blockIdx.z, y = blockIdx.y, x0 = blockIdx.x * 32;
    int tx = threadIdx.x, ty = threadIdx.y;  // 32 x 8
    #pragma unroll
    for (int c = ty; c < CH; c += 8)
        tile[c][tx] = in[(((size_t)n*CH + c)*HH + y)*WW + x0 + tx];
    __syncthreads();
    int t = ty*32 + tx;
    #pragma unroll
    for (int i = 0; i < 8; i++) {
        int idx = t + i*256;
        int px = idx >> 6, c = idx & 63;
        g_x_nhwc[(((size_t)n*HH + y)*WW + x0 + px)*CH + c] = tile[c][px];
    }
}

// ---------------- K1: offsets + masks for both passes (FFMA2) --------------
__global__ __launch_bounds__(256) void offmask_kernel(
    const float* __restrict__ woh, const float* __restrict__ boh,
    const float* __restrict__ wmh, const float* __restrict__ bmh,
    const float* __restrict__ wov, const float* __restrict__ bov,
    const float* __restrict__ wmv, const float* __restrict__ bmv)
{
    __shared__ float ws[64*6*12];
    int tid = threadIdx.x;
    for (int i = tid; i < 64*6*12; i += 256) {
        int o = i % 12, j = (i/12) % 6, c = i/72;
        float v = 0.f;
        if (o < 6)      v = (j < 3) ? woh[o*192 + c*3 + j] : wov[o*192 + c*3 + (j-3)];
        else if (o < 9) v = (j < 3) ? wmh[(o-6)*192 + c*3 + j] : wmv[(o-6)*192 + c*3 + (j-3)];
        ws[i] = v;
    }
    __syncthreads();

    int row = blockIdx.x*2 + (tid >> 7);
    int x   = tid & 127;
    size_t p = (size_t)row*WW + x;
    int y = row & 127;

    u64 aH01 = 0, aH23 = 0, aH45 = 0, aH67 = 0;
    u64 aV01 = 0, aV23 = 0, aV45 = 0, aV67 = 0;
    float aH8 = 0.f, aV8 = 0.f;

    const float* pc = g_x_nhwc + p*CH;
    bool hl = x > 0, hr = x < WW-1, vu = y > 0, vd = y < HH-1;
    const float* pl = pc - CH;
    const float* pr = pc + CH;
    const float* pu = pc - (size_t)WW*CH;
    const float* pd = pc + (size_t)WW*CH;
    const float4 Z = make_float4(0.f,0.f,0.f,0.f);

    for (int c4 = 0; c4 < 16; c4++) {
        float4 fc = *(const float4*)(pc + c4*4);
        float4 fl = hl ? *(const float4*)(pl + c4*4) : Z;
        float4 fr = hr ? *(const float4*)(pr + c4*4) : Z;
        float4 fu = vu ? *(const float4*)(pu + c4*4) : Z;
        float4 fd = vd ? *(const float4*)(pd + c4*4) : Z;
        #pragma unroll
        for (int cc = 0; cc < 4; cc++) {
            int c = c4*4 + cc;
            float vh[3] = { f4c(fl,cc), f4c(fc,cc), f4c(fr,cc) };
            float vv[3] = { f4c(fu,cc), f4c(fc,cc), f4c(fd,cc) };
            #pragma unroll
            for (int j = 0; j < 3; j++) {
                const float* wb = &ws[(c*6 + j)*12];
                ulonglong2 W0 = *(const ulonglong2*)(wb);
                ulonglong2 W1 = *(const ulonglong2*)(wb + 4);
                float w8 = wb[8];
                float v = vh[j];
                u64 vs = pk2(v, v);
                aH01 = ffma2(vs, W0.x, aH01);
                aH23 = ffma2(vs, W0.y, aH23);
                aH45 = ffma2(vs, W1.x, aH45);
                aH67 = ffma2(vs, W1.y, aH67);
                aH8  = fmaf(v, w8, aH8);

                const float* ub = &ws[(c*6 + j + 3)*12];
                ulonglong2 U0 = *(const ulonglong2*)(ub);
                ulonglong2 U1 = *(const ulonglong2*)(ub + 4);
                float u8 = ub[8];
                float u = vv[j];
                u64 us = pk2(u, u);
                aV01 = ffma2(us, U0.x, aV01);
                aV23 = ffma2(us, U0.y, aV23);
                aV45 = ffma2(us, U1.x, aV45);
                aV67 = ffma2(us, U1.y, aV67);
                aV8  = fmaf(u, u8, aV8);
            }
        }
    }

    float accH[9], accV[9];
    upk2(aH01, accH[0], accH[1]); upk2(aH23, accH[2], accH[3]);
    upk2(aH45, accH[4], accH[5]); upk2(aH67, accH[6], accH[7]); accH[8] = aH8;
    upk2(aV01, accV[0], accV[1]); upk2(aV23, accV[2], accV[3]);
    upk2(aV45, accV[4], accV[5]); upk2(aV67, accV[6], accV[7]); accV[8] = aV8;

    float mh0 = 1.f/(1.f + expf(-(accH[6] + __ldg(bmh+0))));
    float mh1 = 1.f/(1.f + expf(-(accH[7] + __ldg(bmh+1))));
    float mh2 = 1.f/(1.f + expf(-(accH[8] + __ldg(bmh+2))));
    float mv0 = 1.f/(1.f + expf(-(accV[6] + __ldg(bmv+0))));
    float mv1 = 1.f/(1.f + expf(-(accV[7] + __ldg(bmv+1))));
    float mv2 = 1.f/(1.f + expf(-(accV[8] + __ldg(bmv+2))));

    float* oh = g_omh + p*12;
    *(float4*)(oh + 0) = make_float4(accH[0]+__ldg(boh+0), accH[1]+__ldg(boh+1),
                                     accH[2]+__ldg(boh+2), accH[3]+__ldg(boh+3));
    *(float4*)(oh + 4) = make_float4(accH[4]+__ldg(boh+4), accH[5]+__ldg(boh+5), mh0, mh1);
    oh[8] = mh2;
    float* ov = g_omv + p*12;
    *(float4*)(ov + 0) = make_float4(accV[0]+__ldg(bov+0), accV[1]+__ldg(bov+1),
                                     accV[2]+__ldg(bov+2), accV[3]+__ldg(bov+3));
    *(float4*)(ov + 4) = make_float4(accV[4]+__ldg(bov+4), accV[5]+__ldg(bov+5), mv0, mv1);
    ov[8] = mv2;
}

// ---------------- K2/K3: deformable axial pass (GEMM-tiled) ----------------
// Block = 256 threads, tile = 128 pixels (one row) x 64 outputs.
// smem layout (dynamic floats):
//   ws2 [3][32][64][2]    : 12288   (channel-pair-interleaved weights)
//   valb[16][129][4]      : 8256    (staged bilinear samples, 1 tap)
//   cww [3][128][4]       : 1536    (corner weights, premult mask)
//   cbase[3][128][4] ints : 1536
#define SM_WS2   0
#define SM_VALB  12288
#define SM_CWW   (12288 + 8256)
#define SM_CB    (SM_CWW + 1536)
#define SM_FLOATS (SM_CB + 1536)

template<int VERT, int OUT_NCHW>
__global__ __launch_bounds__(256, 2) void pass_kernel(
    const float* __restrict__ src,   // NHWC input
    const float* __restrict__ om,    // stride-12 offset/mask records
    const float* __restrict__ wg2,   // reformatted weights [3][32][64][2]
    const float* __restrict__ bias,  // [64]
    float* __restrict__ dst)
{
    extern __shared__ float smem[];
    float* ws2  = smem + SM_WS2;
    float* valb = smem + SM_VALB;
    float* cww  = smem + SM_CWW;
    int*   cbase = (int*)(smem + SM_CB);

    int tid = threadIdx.x;
    int row = blockIdx.x;            // n*H + y
    int n = row >> 7, y = row & 127;

    // stage weights (coalesced float4 copy from pre-reformatted global)
    {
        const float4* s4 = (const float4*)wg2;
        float4* d4 = (float4*)ws2;
        #pragma unroll
        for (int i = 0; i < 12; i++)
            d4[tid + i*256] = s4[tid + i*256];
    }

    // per-pixel, per-tap corner weights + clamped base offsets
    for (int t = tid; t < 384; t += 256) {
        int k = t >> 7, xp = t & 127;
        const float* omb = om + ((size_t)row*WW + xp)*12;
        float dyk = omb[2*k], dxk = omb[2*k + 1], mkk = omb[6 + k];
        float py = (float)y + dyk + (VERT ? (float)(k-1) : 0.f);
        float pxf = (float)xp + dxk + (VERT ? 0.f : (float)(k-1));
        float y0f = floorf(py), x0f = floorf(pxf);
        float wy = py - y0f, wx = pxf - x0f;
        int iy0 = (int)y0f, ix0 = (int)x0f;
        int iy1 = iy0 + 1,  ix1 = ix0 + 1;
        float vy0 = (iy0 >= 0 && iy0 < HH) ? 1.f : 0.f;
        float vy1 = (iy1 >= 0 && iy1 < HH) ? 1.f : 0.f;
        float vx0 = (ix0 >= 0 && ix0 < WW) ? 1.f : 0.f;
        float vx1 = (ix1 >= 0 && ix1 < WW) ? 1.f : 0.f;
        float* cw = &cww[(k*128 + xp)*4];
        cw[0] = (1.f-wy)*(1.f-wx)*vy0*vx0*mkk;
        cw[1] = (1.f-wy)*wx      *vy0*vx1*mkk;
        cw[2] = wy*(1.f-wx)      *vy1*vx0*mkk;
        cw[3] = wy*wx            *vy1*vx1*mkk;
        int cy0 = min(max(iy0,0),HH-1), cy1 = min(max(iy1,0),HH-1);
        int cx0 = min(max(ix0,0),WW-1), cx1 = min(max(ix1,0),WW-1);
        int* cb = &cbase[(k*128 + xp)*4];
        cb[0] = ((n*HH + cy0)*WW + cx0)*CH;
        cb[1] = ((n*HH + cy0)*WW + cx1)*CH;
        cb[2] = ((n*HH + cy1)*WW + cx0)*CH;
        cb[3] = ((n*HH + cy1)*WW + cx1)*CH;
    }
    __syncthreads();

    int lane = tid & 31, wid = tid >> 5;
    int p8 = lane >> 3, c8l = lane & 7;      // phase-A lane roles
    int pg = tid >> 4, og = tid & 15;        // phase-B tile: px=pg*8.., o=og*4..

    u64 acc[8][4];
    #pragma unroll
    for (int i = 0; i < 8; i++)
        #pragma unroll
        for (int j = 0; j < 4; j++) acc[i][j] = 0ull;

    for (int k = 0; k < 3; k++) {
        if (k) __syncthreads();   // valb reuse: previous GEMM done

        // -------- Phase A: stage bilinear samples for this tap --------
        #pragma unroll
        for (int i = 0; i < 4; i++) {
            int xp = wid*16 + i*4 + p8;
            const float* cw = &cww[(k*128 + xp)*4];
            const int*   cb = &cbase[(k*128 + xp)*4];
            float w00 = cw[0], w01 = cw[1], w10 = cw[2], w11 = cw[3];
            int b00 = cb[0], b01 = cb[1], b10 = cb[2], b11 = cb[3];
            #pragma unroll
            for (int h = 0; h < 2; h++) {
                int c8 = h*8 + c8l;
                int co = c8*4;
                float4 v00 = *(const float4*)(src + b00 + co);
                float4 v01 = *(const float4*)(src + b01 + co);
                float4 v10 = *(const float4*)(src + b10 + co);
                float4 v11 = *(const float4*)(src + b11 + co);
                float4 r;
                r.x = fmaf(w00,v00.x, fmaf(w01,v01.x, fmaf(w10,v10.x, w11*v11.x)));
                r.y = fmaf(w00,v00.y, fmaf(w01,v01.y, fmaf(w10,v10.y, w11*v11.y)));
                r.z = fmaf(w00,v00.z, fmaf(w01,v01.z, fmaf(w10,v10.z, w11*v11.z)));
                r.w = fmaf(w00,v00.w, fmaf(w01,v01.w, fmaf(w10,v10.w, w11*v11.w)));
                *(float4*)&valb[(c8*129 + xp)*4] = r;
            }
        }
        __syncthreads();

        // -------- Phase B: GEMM accumulate (LDS.128, 2 channel-pairs/iter) --
        const float* wsk = ws2 + k*4096;
        #pragma unroll 2
        for (int c8 = 0; c8 < 16; c8++) {
            const float* bb = wsk + c8*256 + og*8;
            ulonglong2 Ba = *(const ulonglong2*)(bb);        // c2=2c8, outs 0-1
            ulonglong2 Bb = *(const ulonglong2*)(bb + 4);    // c2=2c8, outs 2-3
            ulonglong2 Bc = *(const ulonglong2*)(bb + 128);  // c2=2c8+1, outs 0-1
            ulonglong2 Bd = *(const ulonglong2*)(bb + 132);  // c2=2c8+1, outs 2-3
            const float* ab = &valb[(c8*129 + pg*8)*4];
            #pragma unroll
            for (int i = 0; i < 8; i++) {
                ulonglong2 Av = *(const ulonglong2*)(ab + i*4);
                acc[i][0] = ffma2(Av.x, Ba.x, acc[i][0]);
                acc[i][1] = ffma2(Av.x, Ba.y, acc[i][1]);
                acc[i][2] = ffma2(Av.x, Bb.x, acc[i][2]);
                acc[i][3] = ffma2(Av.x, Bb.y, acc[i][3]);
                acc[i][0] = ffma2(Av.y, Bc.x, acc[i][0]);
                acc[i][1] = ffma2(Av.y, Bc.y, acc[i][1]);
                acc[i][2] = ffma2(Av.y, Bd.x, acc[i][2]);
                acc[i][3] = ffma2(Av.y, Bd.y, acc[i][3]);
            }
        }
    }

    // -------- finalize: fold pairs, add bias, store --------
    float4 bv = *(const float4*)(bias + og*4);
    float s[8][4];
    #pragma unroll
    for (int i = 0; i < 8; i++) {
        #pragma unroll
        for (int j = 0; j < 4; j++) {
            float lo, hi; upk2(acc[i][j], lo, hi);
            s[i][j] = lo + hi + f4c(bv, j);
        }
    }

    if (OUT_NCHW) {
        #pragma unroll
        for (int j = 0; j < 4; j++) {
            float* db = dst + (((size_t)(n*CH + og*4 + j))*HH + y)*WW + pg*8;
            *(float4*)(db)     = make_float4(s[0][j], s[1][j], s[2][j], s[3][j]);
            *(float4*)(db + 4) = make_float4(s[4][j], s[5][j], s[6][j], s[7][j]);
        }
    } else {
        #pragma unroll
        for (int i = 0; i < 8; i++) {
            float* db = dst + ((size_t)row*WW + pg*8 + i)*CH + og*4;
            *(float4*)db = make_float4(s[i][0], s[i][1], s[i][2], s[i][3]);
        }
    }
}

// ---------------- launch ---------------------------------------------------
extern "C" void kernel_launch(void* const* d_in, const int* in_sizes, int n_in,
                              void* d_out, int out_size) {
    const float* x        = (const float*)d_in[0];
    const float* w_off_h  = (const float*)d_in[1];
    const float* b_off_h  = (const float*)d_in[2];
    const float* w_mask_h = (const float*)d_in[3];
    const float* b_mask_h = (const float*)d_in[4];
    const float* w_off_v  = (const float*)d_in[5];
    const float* b_off_v  = (const float*)d_in[6];
    const float* w_mask_v = (const float*)d_in[7];
    const float* b_mask_v = (const float*)d_in[8];
    const float* w_h      = (const float*)d_in[9];
    const float* b_h      = (const float*)d_in[10];
    const float* w_v      = (const float*)d_in[11];
    const float* b_v      = (const float*)d_in[12];
    float* out = (float*)d_out;

    void *xn_p, *xh_p, *omh_p, *omv_p, *w2_p;
    cudaGetSymbolAddress(&xn_p,  g_x_nhwc);
    cudaGetSymbolAddress(&xh_p,  g_xh_nhwc);
    cudaGetSymbolAddress(&omh_p, g_omh);
    cudaGetSymbolAddress(&omv_p, g_omv);
    cudaGetSymbolAddress(&w2_p,  g_w2);
    const float* xn  = (const float*)xn_p;
    float*       xh  = (float*)xh_p;
    const float* omh = (const float*)omh_p;
    const float* omv = (const float*)omv_p;
    const float* w2h = (const float*)w2_p;
    const float* w2v = w2h + 12288;

    int smem_bytes = SM_FLOATS * 4;   // ~94.5 KB
    cudaFuncSetAttribute(pass_kernel<0,0>,
                         cudaFuncAttributeMaxDynamicSharedMemorySize, smem_bytes);
    cudaFuncSetAttribute(pass_kernel<1,1>,
                         cudaFuncAttributeMaxDynamicSharedMemorySize, smem_bytes);

    prep_weights<<<48, 256>>>(w_h, w_v);

    transpose_kernel<<<dim3(WW/32, HH, BB), dim3(32, 8)>>>(x);

    offmask_kernel<<<BB*HH/2, 256>>>(w_off_h, b_off_h, w_mask_h, b_mask_h,
                                     w_off_v, b_off_v, w_mask_v, b_mask_v);

    pass_kernel<0, 0><<<BB*HH, 256, smem_bytes>>>(xn, omh, w2h, b_h, xh);
    pass_kernel<1, 1><<<BB*HH, 256, smem_bytes>>>((const float*)xh, omv, w2v, b_v, out);
}